// round 15
// baseline (speedup 1.0000x reference)
#include <cuda_runtime.h>
#include <cstdint>
#include <math.h>

#define BATCH 4
#define SEQ   1024
#define EMB   1024
#define NH    16
#define HD    64
#define M_TOT (BATCH*SEQ)          // 4096
#define INV_DENOM (1.0f/32.0f)     // 1/sqrt(EMB_DIM)

// Pair permutation: dim d stored at PI(d) so (d, d+4) are adjacent words.
#define PI(d) (2*(((((d)>>3))<<2) + ((d)&3)) + (((d)>>2)&1))

// Scratch (allocation-free: __device__ globals)
static __device__ float g_QA[BATCH*NH*SEQ*128];  // tf32 bits, PAIR-PERMUTED dims
static __device__ float g_KA[BATCH*NH*SEQ*128];  // tf32 bits, PAIR-PERMUTED dims
static __device__ float g_V [BATCH*NH*SEQ*HD];   // tf32 bits (V+P), linear dims
static __device__ float g_O [M_TOT*EMB];         // attention out (fp32)

// ---------------------------------------------------------------------------
// helpers
// ---------------------------------------------------------------------------
__device__ __forceinline__ uint32_t f2tf32(float f) {
    uint32_t u;
    asm("cvt.rna.tf32.f32 %0, %1;" : "=r"(u) : "f"(f));
    return u;
}
__device__ __forceinline__ float rtf(float f) { return __uint_as_float(f2tf32(f)); }

__device__ __forceinline__ void mma_tf32(float c[4], const uint32_t a[4],
                                         const uint32_t b[2]) {
    asm volatile(
        "mma.sync.aligned.m16n8k8.row.col.f32.tf32.tf32.f32 "
        "{%0,%1,%2,%3}, {%4,%5,%6,%7}, {%8,%9}, {%0,%1,%2,%3};"
        : "+f"(c[0]), "+f"(c[1]), "+f"(c[2]), "+f"(c[3])
        : "r"(a[0]), "r"(a[1]), "r"(a[2]), "r"(a[3]), "r"(b[0]), "r"(b[1]));
}

__device__ __forceinline__ void cp16(float* dst, const float* src) {
    uint32_t d = (uint32_t)__cvta_generic_to_shared(dst);
    asm volatile("cp.async.cg.shared.global [%0], [%1], 16;" :: "r"(d), "l"(src));
}

// ---------------------------------------------------------------------------
// TF32 GEMM, 4-stage cp.async pipeline (R13-record config), with Im-half
// production FUSED into the Q/K projection epilogues (replaces im_fill).
// CTA tile 128x256x32, 256 threads = 8 warps (2m x 4n), warp tile 64x64.
// Grid (4,32) = 128 CTAs = one clean sub-wave at 1 CTA/SM.
// ---------------------------------------------------------------------------
#define AS_STRIDE 36
#define BS_STRIDE 264
#define AS_WORDS  (128*AS_STRIDE)   // 4608
#define BS_WORDS  (32*BS_STRIDE)    // 8448
#define STG_WORDS (AS_WORDS + BS_WORDS)       // 13056
#define NSTAGE    4
#define GEMM_SMEM (NSTAGE*STG_WORDS*4)        // 208896 bytes

__device__ __forceinline__ void issue_slab(
    const float* __restrict__ A, const float* __restrict__ Bm,
    float* stage, int t, int m0, int n0, int k0)
{
    float* as = stage;
    float* bs = stage + AS_WORDS;
#pragma unroll
    for (int i = 0; i < 4; ++i) {          // A: 128 x 32
        int f = t + i * 256;
        int row = f >> 3, kc = (f & 7) * 4;
        cp16(as + row * AS_STRIDE + kc, A + (size_t)(m0 + row) * EMB + k0 + kc);
    }
#pragma unroll
    for (int i = 0; i < 8; ++i) {          // B: 32 x 256
        int f = t + i * 256;
        int k = f >> 6, nc = (f & 63) * 4;
        cp16(bs + k * BS_STRIDE + nc, Bm + (size_t)(k0 + k) * EMB + n0 + nc);
    }
    asm volatile("cp.async.commit_group;");
}

template<int MODE>
__device__ __forceinline__ void gemm_store(int row, int col, float v,
    const float* __restrict__ bias, const float* __restrict__ pos,
    const float* __restrict__ Im, float* __restrict__ Out)
{
    v += bias[col];
    if (MODE <= 2) {
        const int bb = row >> 10, ss = row & 1023;
        const int h = col >> 6, d = col & 63;
        v += pos[(size_t)row * HD + d];
        const size_t hs = (size_t)((bb * NH + h) * SEQ + ss);
        if (MODE == 0) {
            g_QA[hs * 128 + PI(d)] = rtf(v * INV_DENOM);
            float im = Im[(size_t)row * EMB + col];
            g_QA[hs * 128 + PI(64 + d)] = rtf(im * INV_DENOM);
        } else if (MODE == 1) {
            g_KA[hs * 128 + PI(d)] = rtf(v);
            float im = Im[(size_t)row * EMB + col];
            g_KA[hs * 128 + PI(64 + d)] = rtf(im);
        } else {
            g_V [hs * HD  + d] = rtf(v);
        }
    } else {
        Out[(size_t)row * EMB + col] = v;
    }
}

template<int MODE>
__global__ void __launch_bounds__(256, 1) gemm_tf32(
    const float* __restrict__ A, const float* __restrict__ Bm,
    const float* __restrict__ bias, const float* __restrict__ pos,
    const float* __restrict__ Im, float* __restrict__ Out)
{
    extern __shared__ float sm[];

    const float* Ain = (MODE == 3) ? g_O : A;
    const int n0   = blockIdx.x * 256;
    const int m0   = blockIdx.y * 128;
    const int t    = threadIdx.x;
    const int lane = t & 31, warp = t >> 5;
    const int gid  = lane >> 2, tid = lane & 3;
    const int wm   = warp >> 2, wn = warp & 3;

    float acc[4][8][4];
#pragma unroll
    for (int mf = 0; mf < 4; ++mf)
#pragma unroll
        for (int nf = 0; nf < 8; ++nf)
#pragma unroll
            for (int j = 0; j < 4; ++j) acc[mf][nf][j] = 0.f;

    issue_slab(Ain, Bm, sm + 0 * STG_WORDS, t, m0, n0, 0);
    issue_slab(Ain, Bm, sm + 1 * STG_WORDS, t, m0, n0, 32);
    issue_slab(Ain, Bm, sm + 2 * STG_WORDS, t, m0, n0, 64);

    for (int i = 0; i < 32; ++i) {
        if (i < 30)       asm volatile("cp.async.wait_group 2;");
        else if (i == 30) asm volatile("cp.async.wait_group 1;");
        else              asm volatile("cp.async.wait_group 0;");
        __syncthreads();   // slab i ready; slab i-1's readers all retired

        if (i + 3 < 32)
            issue_slab(Ain, Bm, sm + ((i + 3) & 3) * STG_WORDS, t, m0, n0, (i + 3) * 32);

        const float* as = sm + (i & 3) * STG_WORDS;
        const float* bs = as + AS_WORDS;
#pragma unroll
        for (int kk = 0; kk < 32; kk += 8) {
            uint32_t a[4][4], b[8][2];
#pragma unroll
            for (int mf = 0; mf < 4; ++mf) {
                const float* p = as + (wm * 64 + mf * 16 + gid) * AS_STRIDE + kk + tid;
                a[mf][0] = f2tf32(p[0]);
                a[mf][1] = f2tf32(p[8 * AS_STRIDE]);
                a[mf][2] = f2tf32(p[4]);
                a[mf][3] = f2tf32(p[8 * AS_STRIDE + 4]);
            }
#pragma unroll
            for (int nf = 0; nf < 8; ++nf) {
                const float* p = bs + (kk + tid) * BS_STRIDE + wn * 64 + nf * 8 + gid;
                b[nf][0] = f2tf32(p[0]);
                b[nf][1] = f2tf32(p[4 * BS_STRIDE]);
            }
#pragma unroll
            for (int mf = 0; mf < 4; ++mf)
#pragma unroll
                for (int nf = 0; nf < 8; ++nf)
                    mma_tf32(acc[mf][nf], a[mf], b[nf]);
        }
    }

#pragma unroll
    for (int mf = 0; mf < 4; ++mf) {
        const int r0 = m0 + wm * 64 + mf * 16 + gid;
#pragma unroll
        for (int nf = 0; nf < 8; ++nf) {
            const int c0 = n0 + wn * 64 + nf * 8 + tid * 2;
            gemm_store<MODE>(r0,     c0,     acc[mf][nf][0], bias, pos, Im, Out);
            gemm_store<MODE>(r0,     c0 + 1, acc[mf][nf][1], bias, pos, Im, Out);
            gemm_store<MODE>(r0 + 8, c0,     acc[mf][nf][2], bias, pos, Im, Out);
            gemm_store<MODE>(r0 + 8, c0 + 1, acc[mf][nf][3], bias, pos, Im, Out);
        }
    }
}

// ---------------------------------------------------------------------------
// TF32 MMA flash attention, Q-TILE 128 (halved K/V L2 traffic).
// 256 threads = 8 warps, each owning 16 query rows (per-warp structure
// identical to the R13 kernel). Q staged across both K buffers (64 KB),
// K double-buffered + V prefetched with the R12 group discipline.
// Smem: Kb0[64*128] Kb1[64*128] Vs[64*64] Ps[128*68] = 116736 B -> 1 CTA/SM.
// ---------------------------------------------------------------------------
#define SWZV(r, c) ((c) ^ (((r) & 7) << 3))
#define ATT_SMEM ((2*64*128 + 64*64 + 128*68) * 4)   // 116736

__global__ void __launch_bounds__(256, 1) attn_mma()
{
    extern __shared__ float smA[];
    float* Kb0 = smA;                 // K buffer 0 (Q rows 0-63 staging)
    float* Kb1 = smA + 64 * 128;      // K buffer 1 (Q rows 64-127 staging)
    float* Vs  = smA + 2 * 64 * 128;  // [64][64] swizzled
    float* Ps  = Vs + 64 * 64;        // [128][68]

    const int t    = threadIdx.x;
    const int lane = t & 31, warp = t >> 5;          // warp 0..7
    const int gid  = lane >> 2, tid = lane & 3;
    const int qt = blockIdx.x, h = blockIdx.y, b = blockIdx.z;
    const size_t head = (size_t)(b * NH + h);
    const float* Qg = g_QA + head * SEQ * 128 + (size_t)qt * 128 * 128;
    const float* Kg = g_KA + head * SEQ * 128;
    const float* Vg = g_V  + head * SEQ * HD;

    // Prologue: stage Q (128 rows) across Kb0 (rows 0-63) + Kb1 (rows 64-127)
#pragma unroll
    for (int i = 0; i < 16; ++i) {
        int f = t + i * 256;
        int r = f >> 5, j = f & 31;                  // r in 0..127
        float* qb = (r < 64) ? Kb0 : Kb1;
        int lr = r & 63;
        cp16(qb + lr * 128 + 4 * (j ^ ((lr & 3) << 1)), Qg + (size_t)r * 128 + j * 4);
    }
    asm volatile("cp.async.commit_group;");
    asm volatile("cp.async.wait_group 0;");
    __syncthreads();

    // Q fragments (rows r0, r0+8 are in the same buffer: r0&63 <= 55)
    uint32_t aQ[16][4];
    const int r0 = warp * 16 + gid;                  // 0..127
    const float* Qbuf = (r0 < 64) ? Kb0 : Kb1;
    const int lr0 = r0 & 63;
    const int saltQ = (lr0 & 3) << 2;                // == (gid&3)<<2
#pragma unroll
    for (int ks = 0; ks < 16; ++ks) {
        const int ii = (ks * 4 + tid) ^ saltQ;
        float2 q0 = *(const float2*)(Qbuf + lr0 * 128 + 2 * ii);
        float2 q1 = *(const float2*)(Qbuf + (lr0 + 8) * 128 + 2 * ii);
        aQ[ks][0] = __float_as_uint(q0.x);
        aQ[ks][2] = __float_as_uint(q0.y);
        aQ[ks][1] = __float_as_uint(q1.x);
        aQ[ks][3] = __float_as_uint(q1.y);
    }
    __syncthreads();   // all warps done reading Q before K(0) overwrites Kb0

    // Kick off K(0) into Kb0
#pragma unroll
    for (int i = 0; i < 8; ++i) {
        int f = t + i * 256;
        int r = f >> 5, j = f & 31;                  // r in 0..63
        cp16(Kb0 + r * 128 + 4 * (j ^ ((r & 3) << 1)), Kg + (size_t)r * 128 + j * 4);
    }
    asm volatile("cp.async.commit_group;");

    float m0v = -1e30f, m1v = -1e30f, l0 = 0.f, l1 = 0.f;
    float oAcc[8][4];
#pragma unroll
    for (int nf = 0; nf < 8; ++nf)
#pragma unroll
        for (int j = 0; j < 4; ++j) oAcc[nf][j] = 0.f;

    for (int kt = 0; kt < 16; ++kt) {
        float* Kcur = (kt & 1) ? Kb1 : Kb0;
        float* Knxt = (kt & 1) ? Kb0 : Kb1;

        // Issue V(kt) [group], then K(kt+1) [group]
#pragma unroll
        for (int i = 0; i < 4; ++i) {
            int f = t + i * 256;
            int r = f >> 4, c4 = (f & 15) * 4;       // r in 0..63
            cp16(Vs + r * 64 + SWZV(r, c4), Vg + (size_t)(kt * 64 + r) * HD + c4);
        }
        asm volatile("cp.async.commit_group;");
        if (kt < 15) {
#pragma unroll
            for (int i = 0; i < 8; ++i) {
                int f = t + i * 256;
                int r = f >> 5, j = f & 31;
                cp16(Knxt + r * 128 + 4 * (j ^ ((r & 3) << 1)),
                     Kg + (size_t)((kt + 1) * 64 + r) * 128 + j * 4);
            }
            asm volatile("cp.async.commit_group;");
            asm volatile("cp.async.wait_group 2;");   // K(kt) done
        } else {
            asm volatile("cp.async.wait_group 1;");   // K(15) done
        }
        __syncthreads();

        // S = Q K^T over augmented d=128
        float sS[8][4];
#pragma unroll
        for (int nf = 0; nf < 8; ++nf)
#pragma unroll
            for (int j = 0; j < 4; ++j) sS[nf][j] = 0.f;
#pragma unroll
        for (int ks = 0; ks < 16; ++ks) {
            const int ii = (ks * 4 + tid) ^ saltQ;   // K row&3 == gid&3
#pragma unroll
            for (int nf = 0; nf < 8; ++nf) {
                float2 kv = *(const float2*)(Kcur + (nf * 8 + gid) * 128 + 2 * ii);
                uint32_t b2[2];
                b2[0] = __float_as_uint(kv.x);
                b2[1] = __float_as_uint(kv.y);
                mma_tf32(sS[nf], aQ[ks], b2);
            }
        }

        // Online softmax
        float mx0 = -1e30f, mx1 = -1e30f;
#pragma unroll
        for (int nf = 0; nf < 8; ++nf) {
            mx0 = fmaxf(mx0, fmaxf(sS[nf][0], sS[nf][1]));
            mx1 = fmaxf(mx1, fmaxf(sS[nf][2], sS[nf][3]));
        }
#pragma unroll
        for (int off = 1; off <= 2; off <<= 1) {
            mx0 = fmaxf(mx0, __shfl_xor_sync(0xffffffffu, mx0, off));
            mx1 = fmaxf(mx1, __shfl_xor_sync(0xffffffffu, mx1, off));
        }
        const float mn0 = fmaxf(m0v, mx0), mn1 = fmaxf(m1v, mx1);
        const float sc0 = __expf(m0v - mn0), sc1 = __expf(m1v - mn1);
        float rs0 = 0.f, rs1 = 0.f;
#pragma unroll
        for (int nf = 0; nf < 8; ++nf) {
            sS[nf][0] = __expf(sS[nf][0] - mn0);
            sS[nf][1] = __expf(sS[nf][1] - mn0);
            sS[nf][2] = __expf(sS[nf][2] - mn1);
            sS[nf][3] = __expf(sS[nf][3] - mn1);
            rs0 += sS[nf][0] + sS[nf][1];
            rs1 += sS[nf][2] + sS[nf][3];
        }
#pragma unroll
        for (int off = 1; off <= 2; off <<= 1) {
            rs0 += __shfl_xor_sync(0xffffffffu, rs0, off);
            rs1 += __shfl_xor_sync(0xffffffffu, rs1, off);
        }
        l0 = l0 * sc0 + rs0;
        l1 = l1 * sc1 + rs1;
        m0v = mn0; m1v = mn1;
#pragma unroll
        for (int nf = 0; nf < 8; ++nf) {
            oAcc[nf][0] *= sc0; oAcc[nf][1] *= sc0;
            oAcc[nf][2] *= sc1; oAcc[nf][3] *= sc1;
            *(float2*)(Ps + r0 * 68 + nf * 8 + 2 * tid) =
                make_float2(sS[nf][0], sS[nf][1]);
            *(float2*)(Ps + (r0 + 8) * 68 + nf * 8 + 2 * tid) =
                make_float2(sS[nf][2], sS[nf][3]);
        }
        __syncwarp();   // Ps rows are warp-private

        // Wait for V(kt) (K(kt+1) may remain in flight)
        if (kt < 15) asm volatile("cp.async.wait_group 1;");
        else         asm volatile("cp.async.wait_group 0;");
        __syncthreads();

        // O += P @ V
#pragma unroll
        for (int ks = 0; ks < 8; ++ks) {
            uint32_t aP[4];
            const float* pp = Ps + r0 * 68 + ks * 8 + tid;
            aP[0] = f2tf32(pp[0]);
            aP[1] = f2tf32(pp[8 * 68]);
            aP[2] = f2tf32(pp[4]);
            aP[3] = f2tf32(pp[8 * 68 + 4]);
            const int vrow = ks * 8 + tid;           // vrow&7 == tid
#pragma unroll
            for (int nf = 0; nf < 8; ++nf) {
                uint32_t b2[2];
                b2[0] = __float_as_uint(Vs[vrow * 64       + SWZV(tid,     nf * 8 + gid)]);
                b2[1] = __float_as_uint(Vs[(vrow + 4) * 64 + SWZV(tid + 4, nf * 8 + gid)]);
                mma_tf32(oAcc[nf], aP, b2);
            }
        }
        __syncthreads();   // all PV reads of Vs done before next V issue
    }

    const float i0 = 1.f / l0, i1 = 1.f / l1;
    const int q0 = qt * 128 + r0;
#pragma unroll
    for (int nf = 0; nf < 8; ++nf) {
        const int col = h * HD + nf * 8 + 2 * tid;
        *(float2*)(g_O + (size_t)(b * SEQ + q0) * EMB + col) =
            make_float2(oAcc[nf][0] * i0, oAcc[nf][1] * i0);
        *(float2*)(g_O + (size_t)(b * SEQ + q0 + 8) * EMB + col) =
            make_float2(oAcc[nf][2] * i1, oAcc[nf][3] * i1);
    }
}

// ---------------------------------------------------------------------------
extern "C" void kernel_launch(void* const* d_in, const int* in_sizes, int n_in,
                              void* d_out, int out_size)
{
    const float* Re  = (const float*)d_in[0];
    const float* Im  = (const float*)d_in[1];
    const float* pos = (const float*)d_in[2];
    const float* Wq  = (const float*)d_in[3];
    const float* bq  = (const float*)d_in[4];
    const float* Wk  = (const float*)d_in[5];
    const float* bk  = (const float*)d_in[6];
    const float* Wv  = (const float*)d_in[7];
    const float* bv  = (const float*)d_in[8];
    const float* Wo  = (const float*)d_in[9];
    const float* bo  = (const float*)d_in[10];
    float* out = (float*)d_out;

    static bool attrs_set = false;
    if (!attrs_set) {
        cudaFuncSetAttribute(gemm_tf32<0>, cudaFuncAttributeMaxDynamicSharedMemorySize, GEMM_SMEM);
        cudaFuncSetAttribute(gemm_tf32<1>, cudaFuncAttributeMaxDynamicSharedMemorySize, GEMM_SMEM);
        cudaFuncSetAttribute(gemm_tf32<2>, cudaFuncAttributeMaxDynamicSharedMemorySize, GEMM_SMEM);
        cudaFuncSetAttribute(gemm_tf32<3>, cudaFuncAttributeMaxDynamicSharedMemorySize, GEMM_SMEM);
        cudaFuncSetAttribute(attn_mma,     cudaFuncAttributeMaxDynamicSharedMemorySize, ATT_SMEM);
        attrs_set = true;
    }

    const dim3 gg(EMB / 256, M_TOT / 128);   // (4, 32) = 128 CTAs per launch

    gemm_tf32<0><<<gg, 256, GEMM_SMEM>>>(Re, Wq, bq, pos, Im, nullptr);
    gemm_tf32<1><<<gg, 256, GEMM_SMEM>>>(Re, Wk, bk, pos, Im, nullptr);
    gemm_tf32<2><<<gg, 256, GEMM_SMEM>>>(Re, Wv, bv, pos, nullptr, nullptr);

    attn_mma<<<dim3(8, NH, BATCH), 256, ATT_SMEM>>>();

    gemm_tf32<3><<<gg, 256, GEMM_SMEM>>>(nullptr, Wo, bo, nullptr, nullptr, out);
}

// round 16
// speedup vs baseline: 1.0484x; 1.0484x over previous
#include <cuda_runtime.h>
#include <cstdint>
#include <math.h>

#define BATCH 4
#define SEQ   1024
#define EMB   1024
#define NH    16
#define HD    64
#define M_TOT (BATCH*SEQ)          // 4096
#define INV_DENOM (1.0f/32.0f)     // 1/sqrt(EMB_DIM)

// Pair permutation: dim d stored at PI(d) so (d, d+4) are adjacent words.
#define PI(d) (2*(((((d)>>3))<<2) + ((d)&3)) + (((d)>>2)&1))

// Scratch (allocation-free: __device__ globals)
static __device__ float g_QA[BATCH*NH*SEQ*128];  // tf32 bits, PAIR-PERMUTED dims
static __device__ float g_KA[BATCH*NH*SEQ*128];  // tf32 bits, PAIR-PERMUTED dims
static __device__ float g_V [BATCH*NH*SEQ*HD];   // tf32 bits (V+P), linear dims
static __device__ float g_O [M_TOT*EMB];         // attention out (fp32)

// ---------------------------------------------------------------------------
// helpers
// ---------------------------------------------------------------------------
__device__ __forceinline__ uint32_t f2tf32(float f) {
    uint32_t u;
    asm("cvt.rna.tf32.f32 %0, %1;" : "=r"(u) : "f"(f));
    return u;
}
__device__ __forceinline__ float rtf(float f) { return __uint_as_float(f2tf32(f)); }

__device__ __forceinline__ void mma_tf32(float c[4], const uint32_t a[4],
                                         const uint32_t b[2]) {
    asm volatile(
        "mma.sync.aligned.m16n8k8.row.col.f32.tf32.tf32.f32 "
        "{%0,%1,%2,%3}, {%4,%5,%6,%7}, {%8,%9}, {%0,%1,%2,%3};"
        : "+f"(c[0]), "+f"(c[1]), "+f"(c[2]), "+f"(c[3])
        : "r"(a[0]), "r"(a[1]), "r"(a[2]), "r"(a[3]), "r"(b[0]), "r"(b[1]));
}

__device__ __forceinline__ void cp16(float* dst, const float* src) {
    uint32_t d = (uint32_t)__cvta_generic_to_shared(dst);
    asm volatile("cp.async.cg.shared.global [%0], [%1], 16;" :: "r"(d), "l"(src));
}

// ---------------------------------------------------------------------------
// TF32 GEMM, 4-stage cp.async pipeline (record config), with Im-half
// production FUSED into the Q/K projection epilogues (replaces im_fill).
// CTA tile 128x256x32, 256 threads = 8 warps (2m x 4n), warp tile 64x64.
// Grid (4,32) = 128 CTAs = one clean sub-wave at 1 CTA/SM.
// ---------------------------------------------------------------------------
#define AS_STRIDE 36
#define BS_STRIDE 264
#define AS_WORDS  (128*AS_STRIDE)   // 4608
#define BS_WORDS  (32*BS_STRIDE)    // 8448
#define STG_WORDS (AS_WORDS + BS_WORDS)       // 13056
#define NSTAGE    4
#define GEMM_SMEM (NSTAGE*STG_WORDS*4)        // 208896 bytes

__device__ __forceinline__ void issue_slab(
    const float* __restrict__ A, const float* __restrict__ Bm,
    float* stage, int t, int m0, int n0, int k0)
{
    float* as = stage;
    float* bs = stage + AS_WORDS;
#pragma unroll
    for (int i = 0; i < 4; ++i) {          // A: 128 x 32
        int f = t + i * 256;
        int row = f >> 3, kc = (f & 7) * 4;
        cp16(as + row * AS_STRIDE + kc, A + (size_t)(m0 + row) * EMB + k0 + kc);
    }
#pragma unroll
    for (int i = 0; i < 8; ++i) {          // B: 32 x 256
        int f = t + i * 256;
        int k = f >> 6, nc = (f & 63) * 4;
        cp16(bs + k * BS_STRIDE + nc, Bm + (size_t)(k0 + k) * EMB + n0 + nc);
    }
    asm volatile("cp.async.commit_group;");
}

template<int MODE>
__device__ __forceinline__ void gemm_store(int row, int col, float v,
    const float* __restrict__ bias, const float* __restrict__ pos,
    const float* __restrict__ Im, float* __restrict__ Out)
{
    v += bias[col];
    if (MODE <= 2) {
        const int bb = row >> 10, ss = row & 1023;
        const int h = col >> 6, d = col & 63;
        v += pos[(size_t)row * HD + d];
        const size_t hs = (size_t)((bb * NH + h) * SEQ + ss);
        if (MODE == 0) {
            g_QA[hs * 128 + PI(d)] = rtf(v * INV_DENOM);
            float im = Im[(size_t)row * EMB + col];
            g_QA[hs * 128 + PI(64 + d)] = rtf(im * INV_DENOM);
        } else if (MODE == 1) {
            g_KA[hs * 128 + PI(d)] = rtf(v);
            float im = Im[(size_t)row * EMB + col];
            g_KA[hs * 128 + PI(64 + d)] = rtf(im);
        } else {
            g_V [hs * HD  + d] = rtf(v);
        }
    } else {
        Out[(size_t)row * EMB + col] = v;
    }
}

template<int MODE>
__global__ void __launch_bounds__(256, 1) gemm_tf32(
    const float* __restrict__ A, const float* __restrict__ Bm,
    const float* __restrict__ bias, const float* __restrict__ pos,
    const float* __restrict__ Im, float* __restrict__ Out)
{
    extern __shared__ float sm[];

    const float* Ain = (MODE == 3) ? g_O : A;
    const int n0   = blockIdx.x * 256;
    const int m0   = blockIdx.y * 128;
    const int t    = threadIdx.x;
    const int lane = t & 31, warp = t >> 5;
    const int gid  = lane >> 2, tid = lane & 3;
    const int wm   = warp >> 2, wn = warp & 3;

    float acc[4][8][4];
#pragma unroll
    for (int mf = 0; mf < 4; ++mf)
#pragma unroll
        for (int nf = 0; nf < 8; ++nf)
#pragma unroll
            for (int j = 0; j < 4; ++j) acc[mf][nf][j] = 0.f;

    issue_slab(Ain, Bm, sm + 0 * STG_WORDS, t, m0, n0, 0);
    issue_slab(Ain, Bm, sm + 1 * STG_WORDS, t, m0, n0, 32);
    issue_slab(Ain, Bm, sm + 2 * STG_WORDS, t, m0, n0, 64);

    for (int i = 0; i < 32; ++i) {
        if (i < 30)       asm volatile("cp.async.wait_group 2;");
        else if (i == 30) asm volatile("cp.async.wait_group 1;");
        else              asm volatile("cp.async.wait_group 0;");
        __syncthreads();   // slab i ready; slab i-1's readers all retired

        if (i + 3 < 32)
            issue_slab(Ain, Bm, sm + ((i + 3) & 3) * STG_WORDS, t, m0, n0, (i + 3) * 32);

        const float* as = sm + (i & 3) * STG_WORDS;
        const float* bs = as + AS_WORDS;
#pragma unroll
        for (int kk = 0; kk < 32; kk += 8) {
            uint32_t a[4][4], b[8][2];
#pragma unroll
            for (int mf = 0; mf < 4; ++mf) {
                const float* p = as + (wm * 64 + mf * 16 + gid) * AS_STRIDE + kk + tid;
                a[mf][0] = f2tf32(p[0]);
                a[mf][1] = f2tf32(p[8 * AS_STRIDE]);
                a[mf][2] = f2tf32(p[4]);
                a[mf][3] = f2tf32(p[8 * AS_STRIDE + 4]);
            }
#pragma unroll
            for (int nf = 0; nf < 8; ++nf) {
                const float* p = bs + (kk + tid) * BS_STRIDE + wn * 64 + nf * 8 + gid;
                b[nf][0] = f2tf32(p[0]);
                b[nf][1] = f2tf32(p[4 * BS_STRIDE]);
            }
#pragma unroll
            for (int mf = 0; mf < 4; ++mf)
#pragma unroll
                for (int nf = 0; nf < 8; ++nf)
                    mma_tf32(acc[mf][nf], a[mf], b[nf]);
        }
    }

#pragma unroll
    for (int mf = 0; mf < 4; ++mf) {
        const int r0 = m0 + wm * 64 + mf * 16 + gid;
#pragma unroll
        for (int nf = 0; nf < 8; ++nf) {
            const int c0 = n0 + wn * 64 + nf * 8 + tid * 2;
            gemm_store<MODE>(r0,     c0,     acc[mf][nf][0], bias, pos, Im, Out);
            gemm_store<MODE>(r0,     c0 + 1, acc[mf][nf][1], bias, pos, Im, Out);
            gemm_store<MODE>(r0 + 8, c0,     acc[mf][nf][2], bias, pos, Im, Out);
            gemm_store<MODE>(r0 + 8, c0 + 1, acc[mf][nf][3], bias, pos, Im, Out);
        }
    }
}

// ---------------------------------------------------------------------------
// TF32 MMA flash attention — R13 RECORD VERSION verbatim (q-tile 64,
// 128 threads, 2 CTAs/SM, pipelined K double-buffer + V prefetch,
// pair-permuted K/Q with LDS.64 fragments).
// ---------------------------------------------------------------------------
#define SWZV(r, c) ((c) ^ (((r) & 7) << 3))
#define ATT_SMEM ((2*64*128 + 64*64 + 64*68) * 4)   // 99328

__global__ void __launch_bounds__(128, 2) attn_mma()
{
    extern __shared__ float smA[];
    float* Kb0 = smA;
    float* Kb1 = smA + 64 * 128;
    float* Vs  = smA + 2 * 64 * 128;
    float* Ps  = Vs + 64 * 64;

    const int t    = threadIdx.x;
    const int lane = t & 31, warp = t >> 5;
    const int gid  = lane >> 2, tid = lane & 3;
    const int qt = blockIdx.x, h = blockIdx.y, b = blockIdx.z;
    const size_t head = (size_t)(b * NH + h);
    const float* Qg = g_QA + head * SEQ * 128 + (size_t)qt * 64 * 128;
    const float* Kg = g_KA + head * SEQ * 128;
    const float* Vg = g_V  + head * SEQ * HD;

#pragma unroll
    for (int i = 0; i < 16; ++i) {
        int f = t + i * 128;
        int r = f >> 5, j = f & 31;
        cp16(Kb1 + r * 128 + 4 * (j ^ ((r & 3) << 1)), Qg + (size_t)r * 128 + j * 4);
    }
    asm volatile("cp.async.commit_group;");
#pragma unroll
    for (int i = 0; i < 16; ++i) {
        int f = t + i * 128;
        int r = f >> 5, j = f & 31;
        cp16(Kb0 + r * 128 + 4 * (j ^ ((r & 3) << 1)), Kg + (size_t)r * 128 + j * 4);
    }
    asm volatile("cp.async.commit_group;");
    asm volatile("cp.async.wait_group 1;");
    __syncthreads();

    uint32_t aQ[16][4];
    const int r0 = warp * 16 + gid;
    const int saltQ = (gid & 3) << 2;
#pragma unroll
    for (int ks = 0; ks < 16; ++ks) {
        const int ii = (ks * 4 + tid) ^ saltQ;
        float2 q0 = *(const float2*)(Kb1 + r0 * 128 + 2 * ii);
        float2 q1 = *(const float2*)(Kb1 + (r0 + 8) * 128 + 2 * ii);
        aQ[ks][0] = __float_as_uint(q0.x);
        aQ[ks][2] = __float_as_uint(q0.y);
        aQ[ks][1] = __float_as_uint(q1.x);
        aQ[ks][3] = __float_as_uint(q1.y);
    }
    __syncthreads();

    float m0v = -1e30f, m1v = -1e30f, l0 = 0.f, l1 = 0.f;
    float oAcc[8][4];
#pragma unroll
    for (int nf = 0; nf < 8; ++nf)
#pragma unroll
        for (int j = 0; j < 4; ++j) oAcc[nf][j] = 0.f;

    for (int kt = 0; kt < 16; ++kt) {
        float* Kcur = (kt & 1) ? Kb1 : Kb0;
        float* Knxt = (kt & 1) ? Kb0 : Kb1;

#pragma unroll
        for (int i = 0; i < 8; ++i) {
            int f = t + i * 128;
            int r = f >> 4, c4 = (f & 15) * 4;
            cp16(Vs + r * 64 + SWZV(r, c4), Vg + (size_t)(kt * 64 + r) * HD + c4);
        }
        asm volatile("cp.async.commit_group;");
        if (kt < 15) {
#pragma unroll
            for (int i = 0; i < 16; ++i) {
                int f = t + i * 128;
                int r = f >> 5, j = f & 31;
                cp16(Knxt + r * 128 + 4 * (j ^ ((r & 3) << 1)),
                     Kg + (size_t)((kt + 1) * 64 + r) * 128 + j * 4);
            }
            asm volatile("cp.async.commit_group;");
            asm volatile("cp.async.wait_group 2;");
        } else {
            asm volatile("cp.async.wait_group 1;");
        }
        __syncthreads();

        float sS[8][4];
#pragma unroll
        for (int nf = 0; nf < 8; ++nf)
#pragma unroll
            for (int j = 0; j < 4; ++j) sS[nf][j] = 0.f;
#pragma unroll
        for (int ks = 0; ks < 16; ++ks) {
            const int ii = (ks * 4 + tid) ^ saltQ;
#pragma unroll
            for (int nf = 0; nf < 8; ++nf) {
                float2 kv = *(const float2*)(Kcur + (nf * 8 + gid) * 128 + 2 * ii);
                uint32_t b2[2];
                b2[0] = __float_as_uint(kv.x);
                b2[1] = __float_as_uint(kv.y);
                mma_tf32(sS[nf], aQ[ks], b2);
            }
        }

        float mx0 = -1e30f, mx1 = -1e30f;
#pragma unroll
        for (int nf = 0; nf < 8; ++nf) {
            mx0 = fmaxf(mx0, fmaxf(sS[nf][0], sS[nf][1]));
            mx1 = fmaxf(mx1, fmaxf(sS[nf][2], sS[nf][3]));
        }
#pragma unroll
        for (int off = 1; off <= 2; off <<= 1) {
            mx0 = fmaxf(mx0, __shfl_xor_sync(0xffffffffu, mx0, off));
            mx1 = fmaxf(mx1, __shfl_xor_sync(0xffffffffu, mx1, off));
        }
        const float mn0 = fmaxf(m0v, mx0), mn1 = fmaxf(m1v, mx1);
        const float sc0 = __expf(m0v - mn0), sc1 = __expf(m1v - mn1);
        float rs0 = 0.f, rs1 = 0.f;
#pragma unroll
        for (int nf = 0; nf < 8; ++nf) {
            sS[nf][0] = __expf(sS[nf][0] - mn0);
            sS[nf][1] = __expf(sS[nf][1] - mn0);
            sS[nf][2] = __expf(sS[nf][2] - mn1);
            sS[nf][3] = __expf(sS[nf][3] - mn1);
            rs0 += sS[nf][0] + sS[nf][1];
            rs1 += sS[nf][2] + sS[nf][3];
        }
#pragma unroll
        for (int off = 1; off <= 2; off <<= 1) {
            rs0 += __shfl_xor_sync(0xffffffffu, rs0, off);
            rs1 += __shfl_xor_sync(0xffffffffu, rs1, off);
        }
        l0 = l0 * sc0 + rs0;
        l1 = l1 * sc1 + rs1;
        m0v = mn0; m1v = mn1;
#pragma unroll
        for (int nf = 0; nf < 8; ++nf) {
            oAcc[nf][0] *= sc0; oAcc[nf][1] *= sc0;
            oAcc[nf][2] *= sc1; oAcc[nf][3] *= sc1;
            *(float2*)(Ps + r0 * 68 + nf * 8 + 2 * tid) =
                make_float2(sS[nf][0], sS[nf][1]);
            *(float2*)(Ps + (r0 + 8) * 68 + nf * 8 + 2 * tid) =
                make_float2(sS[nf][2], sS[nf][3]);
        }
        __syncwarp();

        if (kt < 15) asm volatile("cp.async.wait_group 1;");
        else         asm volatile("cp.async.wait_group 0;");
        __syncthreads();

#pragma unroll
        for (int ks = 0; ks < 8; ++ks) {
            uint32_t aP[4];
            const float* pp = Ps + r0 * 68 + ks * 8 + tid;
            aP[0] = f2tf32(pp[0]);
            aP[1] = f2tf32(pp[8 * 68]);
            aP[2] = f2tf32(pp[4]);
            aP[3] = f2tf32(pp[8 * 68 + 4]);
            const int vrow = ks * 8 + tid;
#pragma unroll
            for (int nf = 0; nf < 8; ++nf) {
                uint32_t b2[2];
                b2[0] = __float_as_uint(Vs[vrow * 64       + SWZV(tid,     nf * 8 + gid)]);
                b2[1] = __float_as_uint(Vs[(vrow + 4) * 64 + SWZV(tid + 4, nf * 8 + gid)]);
                mma_tf32(oAcc[nf], aP, b2);
            }
        }
        __syncthreads();
    }

    const float i0 = 1.f / l0, i1 = 1.f / l1;
    const int q0 = qt * 64 + r0;
#pragma unroll
    for (int nf = 0; nf < 8; ++nf) {
        const int col = h * HD + nf * 8 + 2 * tid;
        *(float2*)(g_O + (size_t)(b * SEQ + q0) * EMB + col) =
            make_float2(oAcc[nf][0] * i0, oAcc[nf][1] * i0);
        *(float2*)(g_O + (size_t)(b * SEQ + q0 + 8) * EMB + col) =
            make_float2(oAcc[nf][2] * i1, oAcc[nf][3] * i1);
    }
}

// ---------------------------------------------------------------------------
extern "C" void kernel_launch(void* const* d_in, const int* in_sizes, int n_in,
                              void* d_out, int out_size)
{
    const float* Re  = (const float*)d_in[0];
    const float* Im  = (const float*)d_in[1];
    const float* pos = (const float*)d_in[2];
    const float* Wq  = (const float*)d_in[3];
    const float* bq  = (const float*)d_in[4];
    const float* Wk  = (const float*)d_in[5];
    const float* bk  = (const float*)d_in[6];
    const float* Wv  = (const float*)d_in[7];
    const float* bv  = (const float*)d_in[8];
    const float* Wo  = (const float*)d_in[9];
    const float* bo  = (const float*)d_in[10];
    float* out = (float*)d_out;

    static bool attrs_set = false;
    if (!attrs_set) {
        cudaFuncSetAttribute(gemm_tf32<0>, cudaFuncAttributeMaxDynamicSharedMemorySize, GEMM_SMEM);
        cudaFuncSetAttribute(gemm_tf32<1>, cudaFuncAttributeMaxDynamicSharedMemorySize, GEMM_SMEM);
        cudaFuncSetAttribute(gemm_tf32<2>, cudaFuncAttributeMaxDynamicSharedMemorySize, GEMM_SMEM);
        cudaFuncSetAttribute(gemm_tf32<3>, cudaFuncAttributeMaxDynamicSharedMemorySize, GEMM_SMEM);
        cudaFuncSetAttribute(attn_mma,     cudaFuncAttributeMaxDynamicSharedMemorySize, ATT_SMEM);
        attrs_set = true;
    }

    const dim3 gg(EMB / 256, M_TOT / 128);   // (4, 32) = 128 CTAs per launch

    gemm_tf32<0><<<gg, 256, GEMM_SMEM>>>(Re, Wq, bq, pos, Im, nullptr);
    gemm_tf32<1><<<gg, 256, GEMM_SMEM>>>(Re, Wk, bk, pos, Im, nullptr);
    gemm_tf32<2><<<gg, 256, GEMM_SMEM>>>(Re, Wv, bv, pos, nullptr, nullptr);

    attn_mma<<<dim3(16, NH, BATCH), 128, ATT_SMEM>>>();

    gemm_tf32<3><<<gg, 256, GEMM_SMEM>>>(nullptr, Wo, bo, nullptr, nullptr, out);
}

// round 17
// speedup vs baseline: 1.0897x; 1.0394x over previous
#include <cuda_runtime.h>
#include <cstdint>
#include <math.h>

#define BATCH 4
#define SEQ   1024
#define EMB   1024
#define NH    16
#define HD    64
#define M_TOT (BATCH*SEQ)          // 4096
#define INV_DENOM (1.0f/32.0f)     // 1/sqrt(EMB_DIM)

// Pair permutation: dim d stored at PI(d) so (d, d+4) are adjacent words.
#define PI(d) (2*(((((d)>>3))<<2) + ((d)&3)) + (((d)>>2)&1))

// Scratch (allocation-free: __device__ globals)
static __device__ float g_QA[BATCH*NH*SEQ*128];  // tf32 bits, PAIR-PERMUTED dims
static __device__ float g_KA[BATCH*NH*SEQ*128];  // tf32 bits, PAIR-PERMUTED dims
// g_V: key-pair-interleaved: V[s][d] at (s>>3)*512 + d*8 + ((s&3)<<1) + ((s>>2)&1)
static __device__ float g_V [BATCH*NH*SEQ*HD];
static __device__ float g_O [M_TOT*EMB];         // attention out (fp32)

// ---------------------------------------------------------------------------
// helpers
// ---------------------------------------------------------------------------
__device__ __forceinline__ uint32_t f2tf32(float f) {
    uint32_t u;
    asm("cvt.rna.tf32.f32 %0, %1;" : "=r"(u) : "f"(f));
    return u;
}
__device__ __forceinline__ float rtf(float f) { return __uint_as_float(f2tf32(f)); }

__device__ __forceinline__ void mma_tf32(float c[4], const uint32_t a[4],
                                         const uint32_t b[2]) {
    asm volatile(
        "mma.sync.aligned.m16n8k8.row.col.f32.tf32.tf32.f32 "
        "{%0,%1,%2,%3}, {%4,%5,%6,%7}, {%8,%9}, {%0,%1,%2,%3};"
        : "+f"(c[0]), "+f"(c[1]), "+f"(c[2]), "+f"(c[3])
        : "r"(a[0]), "r"(a[1]), "r"(a[2]), "r"(a[3]), "r"(b[0]), "r"(b[1]));
}

__device__ __forceinline__ void cp16(float* dst, const float* src) {
    uint32_t d = (uint32_t)__cvta_generic_to_shared(dst);
    asm volatile("cp.async.cg.shared.global [%0], [%1], 16;" :: "r"(d), "l"(src));
}

// ---------------------------------------------------------------------------
// TF32 GEMM, 4-stage cp.async pipeline (R13 record config).
// CTA tile 128x256x32, 256 threads = 8 warps (2m x 4n), warp tile 64x64.
// Grid (4,32) = 128 CTAs = one clean sub-wave at 1 CTA/SM.
// ---------------------------------------------------------------------------
#define AS_STRIDE 36
#define BS_STRIDE 264
#define AS_WORDS  (128*AS_STRIDE)   // 4608
#define BS_WORDS  (32*BS_STRIDE)    // 8448
#define STG_WORDS (AS_WORDS + BS_WORDS)       // 13056
#define NSTAGE    4
#define GEMM_SMEM (NSTAGE*STG_WORDS*4)        // 208896 bytes

__device__ __forceinline__ void issue_slab(
    const float* __restrict__ A, const float* __restrict__ Bm,
    float* stage, int t, int m0, int n0, int k0)
{
    float* as = stage;
    float* bs = stage + AS_WORDS;
#pragma unroll
    for (int i = 0; i < 4; ++i) {          // A: 128 x 32
        int f = t + i * 256;
        int row = f >> 3, kc = (f & 7) * 4;
        cp16(as + row * AS_STRIDE + kc, A + (size_t)(m0 + row) * EMB + k0 + kc);
    }
#pragma unroll
    for (int i = 0; i < 8; ++i) {          // B: 32 x 256
        int f = t + i * 256;
        int k = f >> 6, nc = (f & 63) * 4;
        cp16(bs + k * BS_STRIDE + nc, Bm + (size_t)(k0 + k) * EMB + n0 + nc);
    }
    asm volatile("cp.async.commit_group;");
}

template<int MODE>
__device__ __forceinline__ void gemm_store(int row, int col, float v,
    const float* __restrict__ bias, const float* __restrict__ pos,
    float* __restrict__ Out)
{
    v += bias[col];
    if (MODE <= 2) {
        const int bb = row >> 10, ss = row & 1023;
        const int h = col >> 6, d = col & 63;
        v += pos[(size_t)row * HD + d];
        const size_t hs = (size_t)((bb * NH + h) * SEQ + ss);
        if (MODE == 0)      g_QA[hs * 128 + PI(d)] = rtf(v * INV_DENOM);
        else if (MODE == 1) g_KA[hs * 128 + PI(d)] = rtf(v);
        else                g_V [(hs >> 3) * 512 + d * 8
                                 + (((int)hs & 3) << 1) + (((int)hs >> 2) & 1)] = rtf(v);
    } else {
        Out[(size_t)row * EMB + col] = v;
    }
}

template<int MODE>
__global__ void __launch_bounds__(256, 1) gemm_tf32(
    const float* __restrict__ A, const float* __restrict__ Bm,
    const float* __restrict__ bias, const float* __restrict__ pos,
    float* __restrict__ Out)
{
    extern __shared__ float sm[];

    const float* Ain = (MODE == 3) ? g_O : A;
    const int n0   = blockIdx.x * 256;
    const int m0   = blockIdx.y * 128;
    const int t    = threadIdx.x;
    const int lane = t & 31, warp = t >> 5;
    const int gid  = lane >> 2, tid = lane & 3;
    const int wm   = warp >> 2, wn = warp & 3;

    float acc[4][8][4];
#pragma unroll
    for (int mf = 0; mf < 4; ++mf)
#pragma unroll
        for (int nf = 0; nf < 8; ++nf)
#pragma unroll
            for (int j = 0; j < 4; ++j) acc[mf][nf][j] = 0.f;

    issue_slab(Ain, Bm, sm + 0 * STG_WORDS, t, m0, n0, 0);
    issue_slab(Ain, Bm, sm + 1 * STG_WORDS, t, m0, n0, 32);
    issue_slab(Ain, Bm, sm + 2 * STG_WORDS, t, m0, n0, 64);

    for (int i = 0; i < 32; ++i) {
        if (i < 30)       asm volatile("cp.async.wait_group 2;");
        else if (i == 30) asm volatile("cp.async.wait_group 1;");
        else              asm volatile("cp.async.wait_group 0;");
        __syncthreads();   // slab i ready; slab i-1's readers all retired

        if (i + 3 < 32)
            issue_slab(Ain, Bm, sm + ((i + 3) & 3) * STG_WORDS, t, m0, n0, (i + 3) * 32);

        const float* as = sm + (i & 3) * STG_WORDS;
        const float* bs = as + AS_WORDS;
#pragma unroll
        for (int kk = 0; kk < 32; kk += 8) {
            uint32_t a[4][4], b[8][2];
#pragma unroll
            for (int mf = 0; mf < 4; ++mf) {
                const float* p = as + (wm * 64 + mf * 16 + gid) * AS_STRIDE + kk + tid;
                a[mf][0] = f2tf32(p[0]);
                a[mf][1] = f2tf32(p[8 * AS_STRIDE]);
                a[mf][2] = f2tf32(p[4]);
                a[mf][3] = f2tf32(p[8 * AS_STRIDE + 4]);
            }
#pragma unroll
            for (int nf = 0; nf < 8; ++nf) {
                const float* p = bs + (kk + tid) * BS_STRIDE + wn * 64 + nf * 8 + gid;
                b[nf][0] = f2tf32(p[0]);
                b[nf][1] = f2tf32(p[4 * BS_STRIDE]);
            }
#pragma unroll
            for (int mf = 0; mf < 4; ++mf)
#pragma unroll
                for (int nf = 0; nf < 8; ++nf)
                    mma_tf32(acc[mf][nf], a[mf], b[nf]);
        }
    }

#pragma unroll
    for (int mf = 0; mf < 4; ++mf) {
        const int r0 = m0 + wm * 64 + mf * 16 + gid;
#pragma unroll
        for (int nf = 0; nf < 8; ++nf) {
            const int c0 = n0 + wn * 64 + nf * 8 + tid * 2;
            gemm_store<MODE>(r0,     c0,     acc[mf][nf][0], bias, pos, Out);
            gemm_store<MODE>(r0,     c0 + 1, acc[mf][nf][1], bias, pos, Out);
            gemm_store<MODE>(r0 + 8, c0,     acc[mf][nf][2], bias, pos, Out);
            gemm_store<MODE>(r0 + 8, c0 + 1, acc[mf][nf][3], bias, pos, Out);
        }
    }
}

// ---------------------------------------------------------------------------
// Fill Im halves of augmented Q/K buffers (tf32-rounded, pair-permuted).
// Standalone (coalesced) — fusion into the epilogue measured +13us in R16.
// ---------------------------------------------------------------------------
__global__ void im_fill_kernel(const float* __restrict__ Im)
{
    int i = blockIdx.x * 256 + threadIdx.x;      // float4 units
    int d4 = (i & 15) * 4;
    int s  = (i >> 4) & 1023;
    int h  = (i >> 14) & 15;
    int b  = i >> 18;
    float4 v = *(const float4*)&Im[((size_t)(b * SEQ + s)) * EMB + h * HD + d4];
    size_t rowb = ((size_t)((b * NH + h) * SEQ + s)) * 128;
    const int D  = 64 + d4;
    const int p0 = 2 * ((D >> 3) << 2) + ((D >> 2) & 1);
    g_QA[rowb + p0    ] = rtf(v.x * INV_DENOM);
    g_QA[rowb + p0 + 2] = rtf(v.y * INV_DENOM);
    g_QA[rowb + p0 + 4] = rtf(v.z * INV_DENOM);
    g_QA[rowb + p0 + 6] = rtf(v.w * INV_DENOM);
    g_KA[rowb + p0    ] = rtf(v.x);
    g_KA[rowb + p0 + 2] = rtf(v.y);
    g_KA[rowb + p0 + 4] = rtf(v.z);
    g_KA[rowb + p0 + 6] = rtf(v.w);
}

// ---------------------------------------------------------------------------
// TF32 MMA flash attention (R13 record structure) with pair-interleaved V:
// each PV B-fragment is one aligned LDS.64, zero swizzle math, and the V
// tile cp.async is a plain linear 16 KB copy (layout is bank-conflict-free:
// half-warp word addrs gid*8+tid*2 cover all 32 banks).
// ---------------------------------------------------------------------------
#define ATT_SMEM ((2*64*128 + 64*64 + 64*68) * 4)   // 99328

__global__ void __launch_bounds__(128, 2) attn_mma()
{
    extern __shared__ float smA[];
    float* Kb0 = smA;
    float* Kb1 = smA + 64 * 128;
    float* Vs  = smA + 2 * 64 * 128;   // paired layout: [8 grp][64 d][4 p][2 e]
    float* Ps  = Vs + 64 * 64;

    const int t    = threadIdx.x;
    const int lane = t & 31, warp = t >> 5;
    const int gid  = lane >> 2, tid = lane & 3;
    const int qt = blockIdx.x, h = blockIdx.y, b = blockIdx.z;
    const size_t head = (size_t)(b * NH + h);
    const float* Qg = g_QA + head * SEQ * 128 + (size_t)qt * 64 * 128;
    const float* Kg = g_KA + head * SEQ * 128;
    const float* Vg = g_V  + head * SEQ * HD;   // paired blocks, head-aligned

#pragma unroll
    for (int i = 0; i < 16; ++i) {
        int f = t + i * 128;
        int r = f >> 5, j = f & 31;
        cp16(Kb1 + r * 128 + 4 * (j ^ ((r & 3) << 1)), Qg + (size_t)r * 128 + j * 4);
    }
    asm volatile("cp.async.commit_group;");
#pragma unroll
    for (int i = 0; i < 16; ++i) {
        int f = t + i * 128;
        int r = f >> 5, j = f & 31;
        cp16(Kb0 + r * 128 + 4 * (j ^ ((r & 3) << 1)), Kg + (size_t)r * 128 + j * 4);
    }
    asm volatile("cp.async.commit_group;");
    asm volatile("cp.async.wait_group 1;");
    __syncthreads();

    uint32_t aQ[16][4];
    const int r0 = warp * 16 + gid;
    const int saltQ = (gid & 3) << 2;
#pragma unroll
    for (int ks = 0; ks < 16; ++ks) {
        const int ii = (ks * 4 + tid) ^ saltQ;
        float2 q0 = *(const float2*)(Kb1 + r0 * 128 + 2 * ii);
        float2 q1 = *(const float2*)(Kb1 + (r0 + 8) * 128 + 2 * ii);
        aQ[ks][0] = __float_as_uint(q0.x);
        aQ[ks][2] = __float_as_uint(q0.y);
        aQ[ks][1] = __float_as_uint(q1.x);
        aQ[ks][3] = __float_as_uint(q1.y);
    }
    __syncthreads();

    float m0v = -1e30f, m1v = -1e30f, l0 = 0.f, l1 = 0.f;
    float oAcc[8][4];
#pragma unroll
    for (int nf = 0; nf < 8; ++nf)
#pragma unroll
        for (int j = 0; j < 4; ++j) oAcc[nf][j] = 0.f;

    for (int kt = 0; kt < 16; ++kt) {
        float* Kcur = (kt & 1) ? Kb1 : Kb0;
        float* Knxt = (kt & 1) ? Kb0 : Kb1;

        // Issue V(kt): linear 4096-float copy (paired layout preserved)
#pragma unroll
        for (int i = 0; i < 8; ++i) {
            int f = t + i * 128;                 // 16B chunk index 0..1023
            cp16(Vs + f * 4, Vg + (size_t)kt * 4096 + f * 4);
        }
        asm volatile("cp.async.commit_group;");
        if (kt < 15) {
#pragma unroll
            for (int i = 0; i < 16; ++i) {
                int f = t + i * 128;
                int r = f >> 5, j = f & 31;
                cp16(Knxt + r * 128 + 4 * (j ^ ((r & 3) << 1)),
                     Kg + (size_t)((kt + 1) * 64 + r) * 128 + j * 4);
            }
            asm volatile("cp.async.commit_group;");
            asm volatile("cp.async.wait_group 2;");
        } else {
            asm volatile("cp.async.wait_group 1;");
        }
        __syncthreads();

        float sS[8][4];
#pragma unroll
        for (int nf = 0; nf < 8; ++nf)
#pragma unroll
            for (int j = 0; j < 4; ++j) sS[nf][j] = 0.f;
#pragma unroll
        for (int ks = 0; ks < 16; ++ks) {
            const int ii = (ks * 4 + tid) ^ saltQ;
#pragma unroll
            for (int nf = 0; nf < 8; ++nf) {
                float2 kv = *(const float2*)(Kcur + (nf * 8 + gid) * 128 + 2 * ii);
                uint32_t b2[2];
                b2[0] = __float_as_uint(kv.x);
                b2[1] = __float_as_uint(kv.y);
                mma_tf32(sS[nf], aQ[ks], b2);
            }
        }

        float mx0 = -1e30f, mx1 = -1e30f;
#pragma unroll
        for (int nf = 0; nf < 8; ++nf) {
            mx0 = fmaxf(mx0, fmaxf(sS[nf][0], sS[nf][1]));
            mx1 = fmaxf(mx1, fmaxf(sS[nf][2], sS[nf][3]));
        }
#pragma unroll
        for (int off = 1; off <= 2; off <<= 1) {
            mx0 = fmaxf(mx0, __shfl_xor_sync(0xffffffffu, mx0, off));
            mx1 = fmaxf(mx1, __shfl_xor_sync(0xffffffffu, mx1, off));
        }
        const float mn0 = fmaxf(m0v, mx0), mn1 = fmaxf(m1v, mx1);
        const float sc0 = __expf(m0v - mn0), sc1 = __expf(m1v - mn1);
        float rs0 = 0.f, rs1 = 0.f;
#pragma unroll
        for (int nf = 0; nf < 8; ++nf) {
            sS[nf][0] = __expf(sS[nf][0] - mn0);
            sS[nf][1] = __expf(sS[nf][1] - mn0);
            sS[nf][2] = __expf(sS[nf][2] - mn1);
            sS[nf][3] = __expf(sS[nf][3] - mn1);
            rs0 += sS[nf][0] + sS[nf][1];
            rs1 += sS[nf][2] + sS[nf][3];
        }
#pragma unroll
        for (int off = 1; off <= 2; off <<= 1) {
            rs0 += __shfl_xor_sync(0xffffffffu, rs0, off);
            rs1 += __shfl_xor_sync(0xffffffffu, rs1, off);
        }
        l0 = l0 * sc0 + rs0;
        l1 = l1 * sc1 + rs1;
        m0v = mn0; m1v = mn1;
#pragma unroll
        for (int nf = 0; nf < 8; ++nf) {
            oAcc[nf][0] *= sc0; oAcc[nf][1] *= sc0;
            oAcc[nf][2] *= sc1; oAcc[nf][3] *= sc1;
            *(float2*)(Ps + r0 * 68 + nf * 8 + 2 * tid) =
                make_float2(sS[nf][0], sS[nf][1]);
            *(float2*)(Ps + (r0 + 8) * 68 + nf * 8 + 2 * tid) =
                make_float2(sS[nf][2], sS[nf][3]);
        }
        __syncwarp();

        if (kt < 15) asm volatile("cp.async.wait_group 1;");
        else         asm volatile("cp.async.wait_group 0;");
        __syncthreads();

        // O += P @ V : one LDS.64 per B-fragment (paired V layout)
#pragma unroll
        for (int ks = 0; ks < 8; ++ks) {
            uint32_t aP[4];
            const float* pp = Ps + r0 * 68 + ks * 8 + tid;
            aP[0] = f2tf32(pp[0]);
            aP[1] = f2tf32(pp[8 * 68]);
            aP[2] = f2tf32(pp[4]);
            aP[3] = f2tf32(pp[8 * 68 + 4]);
            const float* vb = Vs + ks * 512 + tid * 2;
#pragma unroll
            for (int nf = 0; nf < 8; ++nf) {
                float2 vv = *(const float2*)(vb + (nf * 8 + gid) * 8);
                uint32_t b2[2];
                b2[0] = __float_as_uint(vv.x);
                b2[1] = __float_as_uint(vv.y);
                mma_tf32(oAcc[nf], aP, b2);
            }
        }
        __syncthreads();
    }

    const float i0 = 1.f / l0, i1 = 1.f / l1;
    const int q0 = qt * 64 + r0;
#pragma unroll
    for (int nf = 0; nf < 8; ++nf) {
        const int col = h * HD + nf * 8 + 2 * tid;
        *(float2*)(g_O + (size_t)(b * SEQ + q0) * EMB + col) =
            make_float2(oAcc[nf][0] * i0, oAcc[nf][1] * i0);
        *(float2*)(g_O + (size_t)(b * SEQ + q0 + 8) * EMB + col) =
            make_float2(oAcc[nf][2] * i1, oAcc[nf][3] * i1);
    }
}

// ---------------------------------------------------------------------------
extern "C" void kernel_launch(void* const* d_in, const int* in_sizes, int n_in,
                              void* d_out, int out_size)
{
    const float* Re  = (const float*)d_in[0];
    const float* Im  = (const float*)d_in[1];
    const float* pos = (const float*)d_in[2];
    const float* Wq  = (const float*)d_in[3];
    const float* bq  = (const float*)d_in[4];
    const float* Wk  = (const float*)d_in[5];
    const float* bk  = (const float*)d_in[6];
    const float* Wv  = (const float*)d_in[7];
    const float* bv  = (const float*)d_in[8];
    const float* Wo  = (const float*)d_in[9];
    const float* bo  = (const float*)d_in[10];
    float* out = (float*)d_out;

    static bool attrs_set = false;
    if (!attrs_set) {
        cudaFuncSetAttribute(gemm_tf32<0>, cudaFuncAttributeMaxDynamicSharedMemorySize, GEMM_SMEM);
        cudaFuncSetAttribute(gemm_tf32<1>, cudaFuncAttributeMaxDynamicSharedMemorySize, GEMM_SMEM);
        cudaFuncSetAttribute(gemm_tf32<2>, cudaFuncAttributeMaxDynamicSharedMemorySize, GEMM_SMEM);
        cudaFuncSetAttribute(gemm_tf32<3>, cudaFuncAttributeMaxDynamicSharedMemorySize, GEMM_SMEM);
        cudaFuncSetAttribute(attn_mma,     cudaFuncAttributeMaxDynamicSharedMemorySize, ATT_SMEM);
        attrs_set = true;
    }

    const dim3 gg(EMB / 256, M_TOT / 128);   // (4, 32) = 128 CTAs per launch

    im_fill_kernel<<<4096, 256>>>(Im);
    gemm_tf32<0><<<gg, 256, GEMM_SMEM>>>(Re, Wq, bq, pos, nullptr);
    gemm_tf32<1><<<gg, 256, GEMM_SMEM>>>(Re, Wk, bk, pos, nullptr);
    gemm_tf32<2><<<gg, 256, GEMM_SMEM>>>(Re, Wv, bv, pos, nullptr);

    attn_mma<<<dim3(16, NH, BATCH), 128, ATT_SMEM>>>();

    gemm_tf32<3><<<gg, 256, GEMM_SMEM>>>(nullptr, Wo, bo, nullptr, out);
}